// round 8
// baseline (speedup 1.0000x reference)
#include <cuda_runtime.h>

// AtmLayer fused kernel v3: TWO columns per thread (ILP=2), scalar math,
// all weights in shared memory (broadcast LDS shared by both columns).

#define TPB 256

// ---- compile-time scatter tables: per output row, contributing (gas net, comp idx) ----
// comp idx: 0=h2o 1=h2o_sq 2=o3 3=co2 4=n2o 5=ch4 6=u
__device__ constexpr int NETS[29][7] = {
    {23, 0,52,65,74,77,86},
    {24, 1,53,66,75,78,87},
    {25, 2,54,67,76,79,88},
    {26, 3,80,-1,-1,-1,-1},
    {27, 4,81,-1,-1,-1,-1},
    {28, 5,68,-1,-1,-1,-1},
    {29, 6,69,-1,-1,-1,-1},
    {30, 3,82,-1,-1,-1,-1},
    {31, 4,83,-1,-1,-1,-1},
    {32, 9,70,-1,-1,-1,-1},
    {33,10,71,-1,-1,-1,-1},
    {34,11,84,-1,-1,-1,-1},
    {35,12,85,-1,-1,-1,-1},
    {36,13,72,-1,-1,-1,-1},
    {37,14,73,-1,-1,-1,-1},
    {38,15,89,-1,-1,-1,-1},
    {39,16,90,-1,-1,-1,-1},
    {40,17,55,91,-1,-1,-1},
    {41,18,56,92,-1,-1,-1},
    {42,19,57,93,-1,-1,-1},
    {43,20,58,94,-1,-1,-1},
    {44,21,59,95,-1,-1,-1},
    {45,22,60,96,-1,-1,-1},
    {46,-1,-1,-1,-1,-1,-1},
    {47,-1,-1,-1,-1,-1,-1},
    {48,61,-1,-1,-1,-1,-1},
    {49,62,-1,-1,-1,-1,-1},
    {50,63,97,-1,-1,-1,-1},
    {51,64,98,-1,-1,-1,-1},
};
__device__ constexpr int CIDX[29][7] = {
    {1,0,2,3,4,5,6},
    {1,0,2,3,4,5,6},
    {1,0,2,3,4,5,6},
    {1,0,5,0,0,0,0},
    {1,0,5,0,0,0,0},
    {1,0,3,0,0,0,0},
    {1,0,3,0,0,0,0},
    {1,0,5,0,0,0,0},
    {1,0,5,0,0,0,0},
    {1,0,3,0,0,0,0},
    {1,0,3,0,0,0,0},
    {1,0,5,0,0,0,0},
    {1,0,5,0,0,0,0},
    {1,0,3,0,0,0,0},
    {1,0,3,0,0,0,0},
    {1,0,6,0,0,0,0},
    {1,0,6,0,0,0,0},
    {1,0,2,6,0,0,0},
    {1,0,2,6,0,0,0},
    {1,0,2,6,0,0,0},
    {1,0,2,6,0,0,0},
    {1,0,2,6,0,0,0},
    {1,0,2,6,0,0,0},
    {1,0,0,0,0,0,0},
    {1,0,0,0,0,0,0},
    {1,2,0,0,0,0,0},
    {1,2,0,0,0,0,0},
    {1,2,6,0,0,0,0},
    {1,2,6,0,0,0,0},
};

__device__ __forceinline__ float fast_elu(float x) {
    float e = __expf(x) - 1.0f;
    return x > 0.0f ? x : e;
}

// gas net g evaluated for BOTH columns, sharing one set of weight loads.
__device__ __forceinline__ float2 gas_eval2(int g,
                                            float x0a, float x1a,
                                            float x0b, float x1b,
                                            const float* sW1, const float* sB1,
                                            const float* sW2, const float* sB2)
{
    const float4* w1 = reinterpret_cast<const float4*>(sW1 + g * 16);
    const float4 a0 = w1[0];  // W1[g][0][0..3]
    const float4 a1 = w1[1];  // W1[g][0][4..7]
    const float4 b0 = w1[2];  // W1[g][1][0..3]
    const float4 b1 = w1[3];  // W1[g][1][4..7]
    const float4* bb = reinterpret_cast<const float4*>(sB1 + g * 8);
    const float4 c0 = bb[0], c1 = bb[1];
    const float4* vv = reinterpret_cast<const float4*>(sW2 + g * 8);
    const float4 v0 = vv[0], v1 = vv[1];
    const float bias = sB2[g];
    float accA = bias, accB = bias;
    float hA, hB;
    hA = fast_elu(fmaf(x1a, b0.x, fmaf(x0a, a0.x, c0.x)));
    hB = fast_elu(fmaf(x1b, b0.x, fmaf(x0b, a0.x, c0.x)));
    accA = fmaf(hA, v0.x, accA); accB = fmaf(hB, v0.x, accB);
    hA = fast_elu(fmaf(x1a, b0.y, fmaf(x0a, a0.y, c0.y)));
    hB = fast_elu(fmaf(x1b, b0.y, fmaf(x0b, a0.y, c0.y)));
    accA = fmaf(hA, v0.y, accA); accB = fmaf(hB, v0.y, accB);
    hA = fast_elu(fmaf(x1a, b0.z, fmaf(x0a, a0.z, c0.z)));
    hB = fast_elu(fmaf(x1b, b0.z, fmaf(x0b, a0.z, c0.z)));
    accA = fmaf(hA, v0.z, accA); accB = fmaf(hB, v0.z, accB);
    hA = fast_elu(fmaf(x1a, b0.w, fmaf(x0a, a0.w, c0.w)));
    hB = fast_elu(fmaf(x1b, b0.w, fmaf(x0b, a0.w, c0.w)));
    accA = fmaf(hA, v0.w, accA); accB = fmaf(hB, v0.w, accB);
    hA = fast_elu(fmaf(x1a, b1.x, fmaf(x0a, a1.x, c1.x)));
    hB = fast_elu(fmaf(x1b, b1.x, fmaf(x0b, a1.x, c1.x)));
    accA = fmaf(hA, v1.x, accA); accB = fmaf(hB, v1.x, accB);
    hA = fast_elu(fmaf(x1a, b1.y, fmaf(x0a, a1.y, c1.y)));
    hB = fast_elu(fmaf(x1b, b1.y, fmaf(x0b, a1.y, c1.y)));
    accA = fmaf(hA, v1.y, accA); accB = fmaf(hB, v1.y, accB);
    hA = fast_elu(fmaf(x1a, b1.z, fmaf(x0a, a1.z, c1.z)));
    hB = fast_elu(fmaf(x1b, b1.z, fmaf(x0b, a1.z, c1.z)));
    accA = fmaf(hA, v1.z, accA); accB = fmaf(hB, v1.z, accB);
    hA = fast_elu(fmaf(x1a, b1.w, fmaf(x0a, a1.w, c1.w)));
    hB = fast_elu(fmaf(x1b, b1.w, fmaf(x0b, a1.w, c1.w)));
    accA = fmaf(hA, v1.w, accA); accB = fmaf(hB, v1.w, accB);
    return make_float2(fmaxf(accA, 0.0f), fmaxf(accB, 0.0f));
}

__global__ void __launch_bounds__(TPB, 2)
atm_layer_kernel(const float* __restrict__ temp,
                 const float* __restrict__ pressure,
                 const float* __restrict__ comp_h2o,
                 const float* __restrict__ comp_h2o_sq,
                 const float* __restrict__ comp_o3,
                 const float* __restrict__ comp_co2,
                 const float* __restrict__ comp_n2o,
                 const float* __restrict__ comp_ch4,
                 const float* __restrict__ comp_u,
                 const float* __restrict__ lwp,
                 const float* __restrict__ iwp,
                 const float* __restrict__ mu,
                 const float* __restrict__ mu_bar,
                 const float* __restrict__ gas_W1,   // (99,2,8)
                 const float* __restrict__ gas_b1,   // (99,8)
                 const float* __restrict__ gas_W2,   // (99,8,1)
                 const float* __restrict__ gas_b2,   // (99,1)
                 const float* __restrict__ lw_w,     // (29,1)
                 const float* __restrict__ iw_w,     // (29,1)
                 const float* __restrict__ ext_W1,   // (29,4,16)
                 const float* __restrict__ ext_b1,   // (29,16)
                 const float* __restrict__ ext_W2,   // (29,16,3)
                 const float* __restrict__ ext_b2,   // (29,3)
                 float* __restrict__ out,
                 int B)
{
    __shared__ __align__(16) float sW1[99 * 16];
    __shared__ __align__(16) float sB1[99 * 8];
    __shared__ __align__(16) float sW2[99 * 8];
    __shared__ __align__(16) float sB2[100];
    __shared__ __align__(16) float sEW1[29 * 64];   // transposed [r][j(16)][i(4)]
    __shared__ __align__(16) float sEB1[29 * 16];   // [r][j]
    __shared__ __align__(16) float sEW2[29 * 64];   // [r][j(16)][k(4)] k=3 padded 0
    __shared__ __align__(16) float sEB2[88];
    __shared__ float sLW[29], sIW[29];

    const int tid = threadIdx.x;

    // ---- cooperative weight staging ----
    for (int i = tid; i < 99 * 16; i += TPB) sW1[i] = gas_W1[i];
    for (int i = tid; i < 99 * 8;  i += TPB) sB1[i] = gas_b1[i];
    for (int i = tid; i < 99 * 8;  i += TPB) sW2[i] = gas_W2[i];
    for (int i = tid; i < 99;      i += TPB) sB2[i] = gas_b2[i];
    for (int i = tid; i < 29 * 64; i += TPB) {
        int r = i >> 6, rem = i & 63, ii = rem >> 4, j = rem & 15;
        sEW1[(r << 6) + (j << 2) + ii] = ext_W1[i];       // [i][j] -> [j][i]
    }
    for (int i = tid; i < 29 * 48; i += TPB) {
        int r = i / 48, rem = i % 48, j = rem / 3, k = rem % 3;
        sEW2[(r << 6) + (j << 2) + k] = ext_W2[i];        // pad stride 3 -> 4
    }
    for (int i = tid; i < 29 * 16; i += TPB) sEW2[(i << 2) + 3] = 0.0f;
    for (int i = tid; i < 29 * 16; i += TPB) sEB1[i] = ext_b1[i];
    for (int i = tid; i < 87;      i += TPB) sEB2[i] = ext_b2[i];
    for (int i = tid; i < 29;      i += TPB) { sLW[i] = lw_w[i]; sIW[i] = iw_w[i]; }
    __syncthreads();

    const int t = blockIdx.x * TPB + tid;   // pair index
    const int b0 = 2 * t;
    if (b0 + 1 >= B) return;

    // ---- per-column scalar inputs (float2-coalesced) ----
    const float2 X0 = reinterpret_cast<const float2*>(temp)[t];
    const float2 X1 = reinterpret_cast<const float2*>(pressure)[t];
    float2 c2[7];
    c2[0] = reinterpret_cast<const float2*>(comp_h2o)[t];
    c2[1] = reinterpret_cast<const float2*>(comp_h2o_sq)[t];
    c2[2] = reinterpret_cast<const float2*>(comp_o3)[t];
    c2[3] = reinterpret_cast<const float2*>(comp_co2)[t];
    c2[4] = reinterpret_cast<const float2*>(comp_n2o)[t];
    c2[5] = reinterpret_cast<const float2*>(comp_ch4)[t];
    c2[6] = reinterpret_cast<const float2*>(comp_u)[t];
    const float2 LWP = reinterpret_cast<const float2*>(lwp)[t];
    const float2 IWP = reinterpret_cast<const float2*>(iwp)[t];
    const float2 MU  = reinterpret_cast<const float2*>(mu)[t];
    const float2 MUB = reinterpret_cast<const float2*>(mu_bar)[t];
    const float rmuA  = __fdividef(1.0f, MU.x);
    const float rmuB  = __fdividef(1.0f, MU.y);
    const float rmubA = __fdividef(1.0f, MUB.x);
    const float rmubB = __fdividef(1.0f, MUB.y);

    const unsigned NB = (unsigned)B * 29u;
    float* __restrict__ out_tdir = out;
    float* __restrict__ out_tdif = out + NB;
    float* __restrict__ out_edir = out + 2u * NB;
    float* __restrict__ out_edif = out + 5u * NB;

    // ---- per-row streaming: both columns in flight ----
    #pragma unroll
    for (int r = 0; r < 29; ++r) {
        float tauA = 0.0f, tauB = 0.0f;
        #pragma unroll
        for (int tt7 = 0; tt7 < 7; ++tt7) {
            const int g = NETS[r][tt7];
            if (g >= 0) {
                const float2 ke = gas_eval2(g, X0.x, X1.x, X0.y, X1.y, sW1, sB1, sW2, sB2);
                const float2 cc = c2[CIDX[r][tt7]];
                tauA = fmaf(ke.x, cc.x, tauA);
                tauB = fmaf(ke.y, cc.y, tauB);
            }
        }
        const float lwr = sLW[r], iwr = sIW[r];
        const float tlwA = lwr * LWP.x, tlwB = lwr * LWP.y;
        const float tiwA = iwr * IWP.x, tiwB = iwr * IWP.y;
        const float ttA = tauA + tlwA + tiwA;
        const float ttB = tauB + tlwB + tiwB;
        const float rttA = __fdividef(1.0f, ttA);
        const float rttB = __fdividef(1.0f, ttB);
        const float i1A = tlwA * rttA, i1B = tlwB * rttB;
        const float i2A = tiwA * rttA, i2B = tiwB * rttB;
        const float i3dA = ttA * rmuA,  i3dB = ttB * rmuB;
        const float i3fA = ttA * rmubA, i3fB = ttB * rmubB;

        // ext net r: 4 streams (colA dir/dif, colB dir/dif), shared weight loads
        const float eb0 = sEB2[r * 3 + 0];
        const float eb1 = sEB2[r * 3 + 1];
        const float eb2 = sEB2[r * 3 + 2];
        float adA0 = eb0, adA1 = eb1, adA2 = eb2;
        float afA0 = eb0, afA1 = eb1, afA2 = eb2;
        float adB0 = eb0, adB1 = eb1, adB2 = eb2;
        float afB0 = eb0, afB1 = eb1, afB2 = eb2;
        const float4* w1 = reinterpret_cast<const float4*>(sEW1 + (r << 6));
        const float4* w2 = reinterpret_cast<const float4*>(sEW2 + (r << 6));
        const float*  bb = sEB1 + (r << 4);
        #pragma unroll
        for (int j = 0; j < 16; ++j) {
            const float4 w = w1[j];
            const float bj = bb[j];
            const float baseA = fmaf(i2A, w.y, fmaf(i1A, w.x, bj));
            const float baseB = fmaf(i2B, w.y, fmaf(i1B, w.x, bj));
            const float hdA = fast_elu(fmaf(MU.x,  w.w, fmaf(i3dA, w.z, baseA)));
            const float hfA = fast_elu(fmaf(MUB.x, w.w, fmaf(i3fA, w.z, baseA)));
            const float hdB = fast_elu(fmaf(MU.y,  w.w, fmaf(i3dB, w.z, baseB)));
            const float hfB = fast_elu(fmaf(MUB.y, w.w, fmaf(i3fB, w.z, baseB)));
            const float4 v = w2[j];
            adA0 = fmaf(hdA, v.x, adA0); adA1 = fmaf(hdA, v.y, adA1); adA2 = fmaf(hdA, v.z, adA2);
            afA0 = fmaf(hfA, v.x, afA0); afA1 = fmaf(hfA, v.y, afA1); afA2 = fmaf(hfA, v.z, afA2);
            adB0 = fmaf(hdB, v.x, adB0); adB1 = fmaf(hdB, v.y, adB1); adB2 = fmaf(hdB, v.z, adB2);
            afB0 = fmaf(hfB, v.x, afB0); afB1 = fmaf(hfB, v.y, afB1); afB2 = fmaf(hfB, v.z, afB2);
        }

        const unsigned ebase = ((unsigned)r * (unsigned)B + (unsigned)b0) * 3u;  // 6 contiguous
        // softmax helper (inlined x4)
        {
            const float a0 = fmaxf(adA0, 0.0f), a1 = fmaxf(adA1, 0.0f), a2 = fmaxf(adA2, 0.0f);
            const float m = fmaxf(a0, fmaxf(a1, a2));
            const float e0 = __expf(a0 - m), e1 = __expf(a1 - m), e2 = __expf(a2 - m);
            const float inv = __fdividef(1.0f, e0 + e1 + e2);
            const float b0v = fmaxf(adB0, 0.0f), b1v = fmaxf(adB1, 0.0f), b2v = fmaxf(adB2, 0.0f);
            const float mB = fmaxf(b0v, fmaxf(b1v, b2v));
            const float f0 = __expf(b0v - mB), f1 = __expf(b1v - mB), f2 = __expf(b2v - mB);
            const float invB = __fdividef(1.0f, f0 + f1 + f2);
            reinterpret_cast<float2*>(out_edir + ebase)[0] = make_float2(e0 * inv, e1 * inv);
            reinterpret_cast<float2*>(out_edir + ebase)[1] = make_float2(e2 * inv, f0 * invB);
            reinterpret_cast<float2*>(out_edir + ebase)[2] = make_float2(f1 * invB, f2 * invB);
        }
        {
            const float a0 = fmaxf(afA0, 0.0f), a1 = fmaxf(afA1, 0.0f), a2 = fmaxf(afA2, 0.0f);
            const float m = fmaxf(a0, fmaxf(a1, a2));
            const float e0 = __expf(a0 - m), e1 = __expf(a1 - m), e2 = __expf(a2 - m);
            const float inv = __fdividef(1.0f, e0 + e1 + e2);
            const float b0v = fmaxf(afB0, 0.0f), b1v = fmaxf(afB1, 0.0f), b2v = fmaxf(afB2, 0.0f);
            const float mB = fmaxf(b0v, fmaxf(b1v, b2v));
            const float f0 = __expf(b0v - mB), f1 = __expf(b1v - mB), f2 = __expf(b2v - mB);
            const float invB = __fdividef(1.0f, f0 + f1 + f2);
            reinterpret_cast<float2*>(out_edif + ebase)[0] = make_float2(e0 * inv, e1 * inv);
            reinterpret_cast<float2*>(out_edif + ebase)[1] = make_float2(e2 * inv, f0 * invB);
            reinterpret_cast<float2*>(out_edif + ebase)[2] = make_float2(f1 * invB, f2 * invB);
        }
        const unsigned tbase = (unsigned)r * (unsigned)B + (unsigned)b0;
        reinterpret_cast<float2*>(out_tdir + tbase)[0] = make_float2(__expf(-i3dA), __expf(-i3dB));
        reinterpret_cast<float2*>(out_tdif + tbase)[0] = make_float2(__expf(-i3fA), __expf(-i3fB));
    }
}

extern "C" void kernel_launch(void* const* d_in, const int* in_sizes, int n_in,
                              void* d_out, int out_size)
{
    const int B = in_sizes[0];
    const int pairs = B / 2;
    const int blocks = (pairs + TPB - 1) / TPB;
    atm_layer_kernel<<<blocks, TPB>>>(
        (const float*)d_in[0],  (const float*)d_in[1],  (const float*)d_in[2],
        (const float*)d_in[3],  (const float*)d_in[4],  (const float*)d_in[5],
        (const float*)d_in[6],  (const float*)d_in[7],  (const float*)d_in[8],
        (const float*)d_in[9],  (const float*)d_in[10], (const float*)d_in[11],
        (const float*)d_in[12], (const float*)d_in[13], (const float*)d_in[14],
        (const float*)d_in[15], (const float*)d_in[16], (const float*)d_in[17],
        (const float*)d_in[18], (const float*)d_in[19], (const float*)d_in[20],
        (const float*)d_in[21], (const float*)d_in[22],
        (float*)d_out, B);
}

// round 9
// speedup vs baseline: 2.7674x; 2.7674x over previous
#include <cuda_runtime.h>

// AtmLayer v4: parallelize over (row, column). grid = (B/256, 29).
// Each thread computes ONE (r, b) output: its gas nets + ext net (dir+dif).
// Tiny per-block smem (only row r's weights) -> high occupancy.

#define TPB 256

// comp idx: 0=h2o 1=h2o_sq 2=o3 3=co2 4=n2o 5=ch4 6=u
__constant__ int cNETS[29][7] = {
    {23, 0,52,65,74,77,86},
    {24, 1,53,66,75,78,87},
    {25, 2,54,67,76,79,88},
    {26, 3,80,-1,-1,-1,-1},
    {27, 4,81,-1,-1,-1,-1},
    {28, 5,68,-1,-1,-1,-1},
    {29, 6,69,-1,-1,-1,-1},
    {30, 3,82,-1,-1,-1,-1},
    {31, 4,83,-1,-1,-1,-1},
    {32, 9,70,-1,-1,-1,-1},
    {33,10,71,-1,-1,-1,-1},
    {34,11,84,-1,-1,-1,-1},
    {35,12,85,-1,-1,-1,-1},
    {36,13,72,-1,-1,-1,-1},
    {37,14,73,-1,-1,-1,-1},
    {38,15,89,-1,-1,-1,-1},
    {39,16,90,-1,-1,-1,-1},
    {40,17,55,91,-1,-1,-1},
    {41,18,56,92,-1,-1,-1},
    {42,19,57,93,-1,-1,-1},
    {43,20,58,94,-1,-1,-1},
    {44,21,59,95,-1,-1,-1},
    {45,22,60,96,-1,-1,-1},
    {46,-1,-1,-1,-1,-1,-1},
    {47,-1,-1,-1,-1,-1,-1},
    {48,61,-1,-1,-1,-1,-1},
    {49,62,-1,-1,-1,-1,-1},
    {50,63,97,-1,-1,-1,-1},
    {51,64,98,-1,-1,-1,-1},
};
__constant__ int cCIDX[29][7] = {
    {1,0,2,3,4,5,6},
    {1,0,2,3,4,5,6},
    {1,0,2,3,4,5,6},
    {1,0,5,0,0,0,0},
    {1,0,5,0,0,0,0},
    {1,0,3,0,0,0,0},
    {1,0,3,0,0,0,0},
    {1,0,5,0,0,0,0},
    {1,0,5,0,0,0,0},
    {1,0,3,0,0,0,0},
    {1,0,3,0,0,0,0},
    {1,0,5,0,0,0,0},
    {1,0,5,0,0,0,0},
    {1,0,3,0,0,0,0},
    {1,0,3,0,0,0,0},
    {1,0,6,0,0,0,0},
    {1,0,6,0,0,0,0},
    {1,0,2,6,0,0,0},
    {1,0,2,6,0,0,0},
    {1,0,2,6,0,0,0},
    {1,0,2,6,0,0,0},
    {1,0,2,6,0,0,0},
    {1,0,2,6,0,0,0},
    {1,0,0,0,0,0,0},
    {1,0,0,0,0,0,0},
    {1,2,0,0,0,0,0},
    {1,2,0,0,0,0,0},
    {1,2,6,0,0,0,0},
    {1,2,6,0,0,0,0},
};
__constant__ int cCNT[29] = {7,7,7,3,3,3,3,3,3,3,3,3,3,3,3,3,3,4,4,4,4,4,4,1,1,2,2,3,3};

__device__ __forceinline__ float fast_elu(float x) {
    float e = __expf(x) - 1.0f;
    return x > 0.0f ? x : e;
}

__global__ void __launch_bounds__(TPB, 4)
atm_row_kernel(const float* __restrict__ temp,
               const float* __restrict__ pressure,
               const float* __restrict__ comp_h2o,
               const float* __restrict__ comp_h2o_sq,
               const float* __restrict__ comp_o3,
               const float* __restrict__ comp_co2,
               const float* __restrict__ comp_n2o,
               const float* __restrict__ comp_ch4,
               const float* __restrict__ comp_u,
               const float* __restrict__ lwp,
               const float* __restrict__ iwp,
               const float* __restrict__ mu,
               const float* __restrict__ mu_bar,
               const float* __restrict__ gas_W1,   // (99,2,8)
               const float* __restrict__ gas_b1,   // (99,8)
               const float* __restrict__ gas_W2,   // (99,8,1)
               const float* __restrict__ gas_b2,   // (99,1)
               const float* __restrict__ lw_w,     // (29,1)
               const float* __restrict__ iw_w,     // (29,1)
               const float* __restrict__ ext_W1,   // (29,4,16)
               const float* __restrict__ ext_b1,   // (29,16)
               const float* __restrict__ ext_W2,   // (29,16,3)
               const float* __restrict__ ext_b2,   // (29,3)
               float* __restrict__ out,
               int B)
{
    // per-net slot: [0..15]=W1, [16..23]=b1, [24..31]=W2, [32]=b2 (stride 36, 16B-aligned)
    __shared__ __align__(16) float sG[7 * 36];
    __shared__ __align__(16) float sEW1[64];   // transposed [j(16)][i(4)]
    __shared__ __align__(16) float sEW2[64];   // [j(16)][k(4)], k=3 zero-padded
    __shared__ __align__(16) float sEB1[16];
    __shared__ const float* sComp[7];
    __shared__ float sMisc[5];                 // lw, iw, eb0, eb1, eb2

    const int r   = blockIdx.y;
    const int tid = threadIdx.x;
    const int cnt = cCNT[r];

    // ---- stage row r's weights (single pass, tid-partitioned) ----
    if (tid < cnt * 33) {
        const int t = tid / 33;
        const int k = tid - t * 33;
        const int g = cNETS[r][t];
        float v;
        if      (k < 16) v = gas_W1[g * 16 + k];
        else if (k < 24) v = gas_b1[g * 8 + (k - 16)];
        else if (k < 32) v = gas_W2[g * 8 + (k - 24)];
        else             v = gas_b2[g];
        sG[t * 36 + k] = v;
    }
    {
        // use threads [232..255] region is unused; do ext with separate ranges
        if (tid < 64) {
            const int ii = tid >> 4, j = tid & 15;
            sEW1[(j << 2) + ii] = ext_W1[r * 64 + tid];   // [i][j] -> [j][i]
        } else if (tid < 112) {
            const int i = tid - 64;
            const int j = i / 3, k = i - j * 3;
            sEW2[(j << 2) + k] = ext_W2[r * 48 + i];      // pad stride 3 -> 4
        } else if (tid < 128) {
            sEW2[((tid - 112) << 2) + 3] = 0.0f;
        } else if (tid < 144) {
            sEB1[tid - 128] = ext_b1[r * 16 + (tid - 128)];
        } else if (tid < 149) {
            const int k = tid - 144;
            float v;
            if      (k == 0) v = lw_w[r];
            else if (k == 1) v = iw_w[r];
            else             v = ext_b2[r * 3 + (k - 2)];
            sMisc[k] = v;
        } else if (tid >= 160 && tid < 160 + 7) {
            const int t = tid - 160;
            if (t < cnt) {
                const float* ptrs[7] = {comp_h2o, comp_h2o_sq, comp_o3, comp_co2,
                                        comp_n2o, comp_ch4, comp_u};
                sComp[t] = ptrs[cCIDX[r][t]];
            }
        }
    }
    __syncthreads();

    const int b = blockIdx.x * TPB + tid;
    if (b >= B) return;

    const float x0 = temp[b];
    const float x1 = pressure[b];

    // ---- gas nets for this row ----
    float tau = 0.0f;
    #pragma unroll
    for (int t = 0; t < 7; ++t) {
        if (t < cnt) {
            const float4* w = reinterpret_cast<const float4*>(sG + t * 36);
            const float4 a0 = w[0], a1 = w[1];   // W1 row 0
            const float4 b0 = w[2], b1 = w[3];   // W1 row 1
            const float4 c0 = w[4], c1 = w[5];   // b1
            const float4 v0 = w[6], v1 = w[7];   // W2
            float acc = sG[t * 36 + 32];
            float h;
            h = fast_elu(fmaf(x1, b0.x, fmaf(x0, a0.x, c0.x))); acc = fmaf(h, v0.x, acc);
            h = fast_elu(fmaf(x1, b0.y, fmaf(x0, a0.y, c0.y))); acc = fmaf(h, v0.y, acc);
            h = fast_elu(fmaf(x1, b0.z, fmaf(x0, a0.z, c0.z))); acc = fmaf(h, v0.z, acc);
            h = fast_elu(fmaf(x1, b0.w, fmaf(x0, a0.w, c0.w))); acc = fmaf(h, v0.w, acc);
            h = fast_elu(fmaf(x1, b1.x, fmaf(x0, a1.x, c1.x))); acc = fmaf(h, v1.x, acc);
            h = fast_elu(fmaf(x1, b1.y, fmaf(x0, a1.y, c1.y))); acc = fmaf(h, v1.y, acc);
            h = fast_elu(fmaf(x1, b1.z, fmaf(x0, a1.z, c1.z))); acc = fmaf(h, v1.z, acc);
            h = fast_elu(fmaf(x1, b1.w, fmaf(x0, a1.w, c1.w))); acc = fmaf(h, v1.w, acc);
            const float ke = fmaxf(acc, 0.0f);
            tau = fmaf(ke, __ldg(sComp[t] + b), tau);
        }
    }

    // ---- cloud terms + ext inputs ----
    const float tlw = sMisc[0] * lwp[b];
    const float tiw = sMisc[1] * iwp[b];
    const float tt  = tau + tlw + tiw;
    const float rtt = __fdividef(1.0f, tt);
    const float i1  = tlw * rtt;
    const float i2  = tiw * rtt;
    const float muv  = mu[b];
    const float mubv = mu_bar[b];
    const float i3d = tt * __fdividef(1.0f, muv);
    const float i3f = tt * __fdividef(1.0f, mubv);

    // ---- ext net (direct + diffuse share weight loads) ----
    const float eb0 = sMisc[2], eb1 = sMisc[3], eb2 = sMisc[4];
    float ad0 = eb0, ad1 = eb1, ad2 = eb2;
    float af0 = eb0, af1 = eb1, af2 = eb2;
    const float4* w1 = reinterpret_cast<const float4*>(sEW1);
    const float4* w2 = reinterpret_cast<const float4*>(sEW2);
    #pragma unroll
    for (int j = 0; j < 16; ++j) {
        const float4 w = w1[j];
        const float bj = sEB1[j];
        const float base = fmaf(i2, w.y, fmaf(i1, w.x, bj));
        const float hd = fast_elu(fmaf(muv,  w.w, fmaf(i3d, w.z, base)));
        const float hf = fast_elu(fmaf(mubv, w.w, fmaf(i3f, w.z, base)));
        const float4 v = w2[j];
        ad0 = fmaf(hd, v.x, ad0); ad1 = fmaf(hd, v.y, ad1); ad2 = fmaf(hd, v.z, ad2);
        af0 = fmaf(hf, v.x, af0); af1 = fmaf(hf, v.y, af1); af2 = fmaf(hf, v.z, af2);
    }
    ad0 = fmaxf(ad0, 0.0f); ad1 = fmaxf(ad1, 0.0f); ad2 = fmaxf(ad2, 0.0f);
    af0 = fmaxf(af0, 0.0f); af1 = fmaxf(af1, 0.0f); af2 = fmaxf(af2, 0.0f);

    const unsigned NB = (unsigned)B * 29u;
    const unsigned rb = (unsigned)r * (unsigned)B + (unsigned)b;

    // softmax (direct)
    {
        const float m = fmaxf(ad0, fmaxf(ad1, ad2));
        const float e0 = __expf(ad0 - m), e1 = __expf(ad1 - m), e2 = __expf(ad2 - m);
        const float inv = __fdividef(1.0f, e0 + e1 + e2);
        float* o = out + 2u * NB + rb * 3u;
        o[0] = e0 * inv; o[1] = e1 * inv; o[2] = e2 * inv;
    }
    // softmax (diffuse)
    {
        const float m = fmaxf(af0, fmaxf(af1, af2));
        const float e0 = __expf(af0 - m), e1 = __expf(af1 - m), e2 = __expf(af2 - m);
        const float inv = __fdividef(1.0f, e0 + e1 + e2);
        float* o = out + 5u * NB + rb * 3u;
        o[0] = e0 * inv; o[1] = e1 * inv; o[2] = e2 * inv;
    }
    out[rb]      = __expf(-i3d);
    out[NB + rb] = __expf(-i3f);
}

extern "C" void kernel_launch(void* const* d_in, const int* in_sizes, int n_in,
                              void* d_out, int out_size)
{
    const int B = in_sizes[0];
    dim3 grid((B + TPB - 1) / TPB, 29);
    atm_row_kernel<<<grid, TPB>>>(
        (const float*)d_in[0],  (const float*)d_in[1],  (const float*)d_in[2],
        (const float*)d_in[3],  (const float*)d_in[4],  (const float*)d_in[5],
        (const float*)d_in[6],  (const float*)d_in[7],  (const float*)d_in[8],
        (const float*)d_in[9],  (const float*)d_in[10], (const float*)d_in[11],
        (const float*)d_in[12], (const float*)d_in[13], (const float*)d_in[14],
        (const float*)d_in[15], (const float*)d_in[16], (const float*)d_in[17],
        (const float*)d_in[18], (const float*)d_in[19], (const float*)d_in[20],
        (const float*)d_in[21], (const float*)d_in[22],
        (float*)d_out, B);
}

// round 10
// speedup vs baseline: 3.0308x; 1.0952x over previous
#include <cuda_runtime.h>

// AtmLayer v5: (row, column-pair) grid; one thread = one row x two columns.
// Compile-time gas-net count via switch dispatch to templated body.

#define TPB 128

// comp idx: 0=h2o 1=h2o_sq 2=o3 3=co2 4=n2o 5=ch4 6=u
__constant__ int cNETS[29][7] = {
    {23, 0,52,65,74,77,86},
    {24, 1,53,66,75,78,87},
    {25, 2,54,67,76,79,88},
    {26, 3,80,-1,-1,-1,-1},
    {27, 4,81,-1,-1,-1,-1},
    {28, 5,68,-1,-1,-1,-1},
    {29, 6,69,-1,-1,-1,-1},
    {30, 3,82,-1,-1,-1,-1},
    {31, 4,83,-1,-1,-1,-1},
    {32, 9,70,-1,-1,-1,-1},
    {33,10,71,-1,-1,-1,-1},
    {34,11,84,-1,-1,-1,-1},
    {35,12,85,-1,-1,-1,-1},
    {36,13,72,-1,-1,-1,-1},
    {37,14,73,-1,-1,-1,-1},
    {38,15,89,-1,-1,-1,-1},
    {39,16,90,-1,-1,-1,-1},
    {40,17,55,91,-1,-1,-1},
    {41,18,56,92,-1,-1,-1},
    {42,19,57,93,-1,-1,-1},
    {43,20,58,94,-1,-1,-1},
    {44,21,59,95,-1,-1,-1},
    {45,22,60,96,-1,-1,-1},
    {46,-1,-1,-1,-1,-1,-1},
    {47,-1,-1,-1,-1,-1,-1},
    {48,61,-1,-1,-1,-1,-1},
    {49,62,-1,-1,-1,-1,-1},
    {50,63,97,-1,-1,-1,-1},
    {51,64,98,-1,-1,-1,-1},
};
__constant__ int cCIDX[29][7] = {
    {1,0,2,3,4,5,6},
    {1,0,2,3,4,5,6},
    {1,0,2,3,4,5,6},
    {1,0,5,0,0,0,0},
    {1,0,5,0,0,0,0},
    {1,0,3,0,0,0,0},
    {1,0,3,0,0,0,0},
    {1,0,5,0,0,0,0},
    {1,0,5,0,0,0,0},
    {1,0,3,0,0,0,0},
    {1,0,3,0,0,0,0},
    {1,0,5,0,0,0,0},
    {1,0,5,0,0,0,0},
    {1,0,3,0,0,0,0},
    {1,0,3,0,0,0,0},
    {1,0,6,0,0,0,0},
    {1,0,6,0,0,0,0},
    {1,0,2,6,0,0,0},
    {1,0,2,6,0,0,0},
    {1,0,2,6,0,0,0},
    {1,0,2,6,0,0,0},
    {1,0,2,6,0,0,0},
    {1,0,2,6,0,0,0},
    {1,0,0,0,0,0,0},
    {1,0,0,0,0,0,0},
    {1,2,0,0,0,0,0},
    {1,2,0,0,0,0,0},
    {1,2,6,0,0,0,0},
    {1,2,6,0,0,0,0},
};
__constant__ int cCNT[29] = {7,7,7,3,3,3,3,3,3,3,3,3,3,3,3,3,3,4,4,4,4,4,4,1,1,2,2,3,3};

__device__ __forceinline__ float fast_elu(float x) {
    float e = __expf(x) - 1.0f;
    return x > 0.0f ? x : e;
}

struct SmemT {
    float sG[7 * 36];      // per net: [0..15]=W1 [16..23]=b1 [24..31]=W2 [32]=b2
    float sEW1[64];        // [j(16)][i(4)]
    float sEW2[64];        // [j(16)][k(4)] pad
    float sEB1[16];
    const float* sComp[7];
    float sMisc[5];        // lw, iw, eb0..2
};

template<int CNT>
__device__ __forceinline__ void row_body(
    SmemT* sm, int r,
    const float* __restrict__ temp, const float* __restrict__ pressure,
    const float* __restrict__ comp_h2o, const float* __restrict__ comp_h2o_sq,
    const float* __restrict__ comp_o3, const float* __restrict__ comp_co2,
    const float* __restrict__ comp_n2o, const float* __restrict__ comp_ch4,
    const float* __restrict__ comp_u,
    const float* __restrict__ lwp, const float* __restrict__ iwp,
    const float* __restrict__ mu, const float* __restrict__ mu_bar,
    const float* __restrict__ gas_W1, const float* __restrict__ gas_b1,
    const float* __restrict__ gas_W2, const float* __restrict__ gas_b2,
    const float* __restrict__ lw_w, const float* __restrict__ iw_w,
    const float* __restrict__ ext_W1, const float* __restrict__ ext_b1,
    const float* __restrict__ ext_W2, const float* __restrict__ ext_b2,
    float* __restrict__ out, int B)
{
    const int tid = threadIdx.x;

    // ---- staging ----
    #pragma unroll
    for (int i = tid; i < CNT * 33; i += TPB) {
        const int t = i / 33;
        const int k = i - t * 33;
        const int g = cNETS[r][t];
        float v;
        if      (k < 16) v = gas_W1[g * 16 + k];
        else if (k < 24) v = gas_b1[g * 8 + (k - 16)];
        else if (k < 32) v = gas_W2[g * 8 + (k - 24)];
        else             v = gas_b2[g];
        sm->sG[t * 36 + k] = v;
    }
    for (int i = tid; i < 64; i += TPB) {
        const int ii = i >> 4, j = i & 15;
        sm->sEW1[(j << 2) + ii] = ext_W1[r * 64 + i];
    }
    for (int i = tid; i < 48; i += TPB) {
        const int j = i / 3, k = i - j * 3;
        sm->sEW2[(j << 2) + k] = ext_W2[r * 48 + i];
    }
    for (int i = tid; i < 16; i += TPB) {
        sm->sEW2[(i << 2) + 3] = 0.0f;
        sm->sEB1[i] = ext_b1[r * 16 + i];
    }
    if (tid < 5) {
        float v;
        if      (tid == 0) v = lw_w[r];
        else if (tid == 1) v = iw_w[r];
        else               v = ext_b2[r * 3 + (tid - 2)];
        sm->sMisc[tid] = v;
    }
    if (tid >= 8 && tid < 8 + CNT) {
        const int t = tid - 8;
        const float* ptrs[7] = {comp_h2o, comp_h2o_sq, comp_o3, comp_co2,
                                comp_n2o, comp_ch4, comp_u};
        sm->sComp[t] = ptrs[cCIDX[r][t]];
    }
    __syncthreads();

    const int p = blockIdx.x * TPB + tid;      // pair index
    const int b0 = 2 * p;
    if (b0 + 1 >= B) return;

    const float2 X0 = reinterpret_cast<const float2*>(temp)[p];
    const float2 X1 = reinterpret_cast<const float2*>(pressure)[p];

    // ---- gas nets for this row, both columns sharing weights ----
    float tauA = 0.0f, tauB = 0.0f;
    #pragma unroll
    for (int t = 0; t < CNT; ++t) {
        const float4* w = reinterpret_cast<const float4*>(sm->sG + t * 36);
        const float4 a0 = w[0], a1 = w[1];
        const float4 w0 = w[2], w1v = w[3];
        const float4 c0 = w[4], c1 = w[5];
        const float4 v0 = w[6], v1 = w[7];
        const float bias = sm->sG[t * 36 + 32];
        float accA = bias, accB = bias;
        float hA, hB;
        hA = fast_elu(fmaf(X1.x, w0.x, fmaf(X0.x, a0.x, c0.x)));
        hB = fast_elu(fmaf(X1.y, w0.x, fmaf(X0.y, a0.x, c0.x)));
        accA = fmaf(hA, v0.x, accA); accB = fmaf(hB, v0.x, accB);
        hA = fast_elu(fmaf(X1.x, w0.y, fmaf(X0.x, a0.y, c0.y)));
        hB = fast_elu(fmaf(X1.y, w0.y, fmaf(X0.y, a0.y, c0.y)));
        accA = fmaf(hA, v0.y, accA); accB = fmaf(hB, v0.y, accB);
        hA = fast_elu(fmaf(X1.x, w0.z, fmaf(X0.x, a0.z, c0.z)));
        hB = fast_elu(fmaf(X1.y, w0.z, fmaf(X0.y, a0.z, c0.z)));
        accA = fmaf(hA, v0.z, accA); accB = fmaf(hB, v0.z, accB);
        hA = fast_elu(fmaf(X1.x, w0.w, fmaf(X0.x, a0.w, c0.w)));
        hB = fast_elu(fmaf(X1.y, w0.w, fmaf(X0.y, a0.w, c0.w)));
        accA = fmaf(hA, v0.w, accA); accB = fmaf(hB, v0.w, accB);
        hA = fast_elu(fmaf(X1.x, w1v.x, fmaf(X0.x, a1.x, c1.x)));
        hB = fast_elu(fmaf(X1.y, w1v.x, fmaf(X0.y, a1.x, c1.x)));
        accA = fmaf(hA, v1.x, accA); accB = fmaf(hB, v1.x, accB);
        hA = fast_elu(fmaf(X1.x, w1v.y, fmaf(X0.x, a1.y, c1.y)));
        hB = fast_elu(fmaf(X1.y, w1v.y, fmaf(X0.y, a1.y, c1.y)));
        accA = fmaf(hA, v1.y, accA); accB = fmaf(hB, v1.y, accB);
        hA = fast_elu(fmaf(X1.x, w1v.z, fmaf(X0.x, a1.z, c1.z)));
        hB = fast_elu(fmaf(X1.y, w1v.z, fmaf(X0.y, a1.z, c1.z)));
        accA = fmaf(hA, v1.z, accA); accB = fmaf(hB, v1.z, accB);
        hA = fast_elu(fmaf(X1.x, w1v.w, fmaf(X0.x, a1.w, c1.w)));
        hB = fast_elu(fmaf(X1.y, w1v.w, fmaf(X0.y, a1.w, c1.w)));
        accA = fmaf(hA, v1.w, accA); accB = fmaf(hB, v1.w, accB);
        const float2 cc = reinterpret_cast<const float2*>(sm->sComp[t])[p];
        tauA = fmaf(fmaxf(accA, 0.0f), cc.x, tauA);
        tauB = fmaf(fmaxf(accB, 0.0f), cc.y, tauB);
    }

    // ---- cloud terms + ext inputs ----
    const float2 LWP = reinterpret_cast<const float2*>(lwp)[p];
    const float2 IWP = reinterpret_cast<const float2*>(iwp)[p];
    const float2 MUv = reinterpret_cast<const float2*>(mu)[p];
    const float2 MUB = reinterpret_cast<const float2*>(mu_bar)[p];
    const float lwr = sm->sMisc[0], iwr = sm->sMisc[1];
    const float tlwA = lwr * LWP.x, tlwB = lwr * LWP.y;
    const float tiwA = iwr * IWP.x, tiwB = iwr * IWP.y;
    const float ttA = tauA + tlwA + tiwA;
    const float ttB = tauB + tlwB + tiwB;
    const float rttA = __fdividef(1.0f, ttA);
    const float rttB = __fdividef(1.0f, ttB);
    const float i1A = tlwA * rttA, i1B = tlwB * rttB;
    const float i2A = tiwA * rttA, i2B = tiwB * rttB;
    const float i3dA = ttA * __fdividef(1.0f, MUv.x);
    const float i3dB = ttB * __fdividef(1.0f, MUv.y);
    const float i3fA = ttA * __fdividef(1.0f, MUB.x);
    const float i3fB = ttB * __fdividef(1.0f, MUB.y);

    // ---- ext net: 4 streams share weight loads ----
    const float eb0 = sm->sMisc[2], eb1 = sm->sMisc[3], eb2 = sm->sMisc[4];
    float adA0 = eb0, adA1 = eb1, adA2 = eb2;
    float afA0 = eb0, afA1 = eb1, afA2 = eb2;
    float adB0 = eb0, adB1 = eb1, adB2 = eb2;
    float afB0 = eb0, afB1 = eb1, afB2 = eb2;
    const float4* w1 = reinterpret_cast<const float4*>(sm->sEW1);
    const float4* w2 = reinterpret_cast<const float4*>(sm->sEW2);
    #pragma unroll
    for (int j = 0; j < 16; ++j) {
        const float4 w = w1[j];
        const float bj = sm->sEB1[j];
        const float baseA = fmaf(i2A, w.y, fmaf(i1A, w.x, bj));
        const float baseB = fmaf(i2B, w.y, fmaf(i1B, w.x, bj));
        const float hdA = fast_elu(fmaf(MUv.x, w.w, fmaf(i3dA, w.z, baseA)));
        const float hfA = fast_elu(fmaf(MUB.x, w.w, fmaf(i3fA, w.z, baseA)));
        const float hdB = fast_elu(fmaf(MUv.y, w.w, fmaf(i3dB, w.z, baseB)));
        const float hfB = fast_elu(fmaf(MUB.y, w.w, fmaf(i3fB, w.z, baseB)));
        const float4 v = w2[j];
        adA0 = fmaf(hdA, v.x, adA0); adA1 = fmaf(hdA, v.y, adA1); adA2 = fmaf(hdA, v.z, adA2);
        afA0 = fmaf(hfA, v.x, afA0); afA1 = fmaf(hfA, v.y, afA1); afA2 = fmaf(hfA, v.z, afA2);
        adB0 = fmaf(hdB, v.x, adB0); adB1 = fmaf(hdB, v.y, adB1); adB2 = fmaf(hdB, v.z, adB2);
        afB0 = fmaf(hfB, v.x, afB0); afB1 = fmaf(hfB, v.y, afB1); afB2 = fmaf(hfB, v.z, afB2);
    }

    const unsigned NB = (unsigned)B * 29u;
    const unsigned rb = (unsigned)r * (unsigned)B + (unsigned)b0;
    const unsigned ebase = rb * 3u;

    // softmax (direct, cols A+B) -> 3 float2 stores
    {
        const float a0 = fmaxf(adA0, 0.0f), a1 = fmaxf(adA1, 0.0f), a2 = fmaxf(adA2, 0.0f);
        const float m = fmaxf(a0, fmaxf(a1, a2));
        const float e0 = __expf(a0 - m), e1 = __expf(a1 - m), e2 = __expf(a2 - m);
        const float inv = __fdividef(1.0f, e0 + e1 + e2);
        const float b0v = fmaxf(adB0, 0.0f), b1v = fmaxf(adB1, 0.0f), b2v = fmaxf(adB2, 0.0f);
        const float mB = fmaxf(b0v, fmaxf(b1v, b2v));
        const float f0 = __expf(b0v - mB), f1 = __expf(b1v - mB), f2 = __expf(b2v - mB);
        const float invB = __fdividef(1.0f, f0 + f1 + f2);
        float2* o = reinterpret_cast<float2*>(out + 2u * NB + ebase);
        o[0] = make_float2(e0 * inv, e1 * inv);
        o[1] = make_float2(e2 * inv, f0 * invB);
        o[2] = make_float2(f1 * invB, f2 * invB);
    }
    // softmax (diffuse)
    {
        const float a0 = fmaxf(afA0, 0.0f), a1 = fmaxf(afA1, 0.0f), a2 = fmaxf(afA2, 0.0f);
        const float m = fmaxf(a0, fmaxf(a1, a2));
        const float e0 = __expf(a0 - m), e1 = __expf(a1 - m), e2 = __expf(a2 - m);
        const float inv = __fdividef(1.0f, e0 + e1 + e2);
        const float b0v = fmaxf(afB0, 0.0f), b1v = fmaxf(afB1, 0.0f), b2v = fmaxf(afB2, 0.0f);
        const float mB = fmaxf(b0v, fmaxf(b1v, b2v));
        const float f0 = __expf(b0v - mB), f1 = __expf(b1v - mB), f2 = __expf(b2v - mB);
        const float invB = __fdividef(1.0f, f0 + f1 + f2);
        float2* o = reinterpret_cast<float2*>(out + 5u * NB + ebase);
        o[0] = make_float2(e0 * inv, e1 * inv);
        o[1] = make_float2(e2 * inv, f0 * invB);
        o[2] = make_float2(f1 * invB, f2 * invB);
    }
    reinterpret_cast<float2*>(out + rb)[0]      = make_float2(__expf(-i3dA), __expf(-i3dB));
    reinterpret_cast<float2*>(out + NB + rb)[0] = make_float2(__expf(-i3fA), __expf(-i3fB));
}

__global__ void __launch_bounds__(TPB)
atm_row_kernel(const float* __restrict__ temp,
               const float* __restrict__ pressure,
               const float* __restrict__ comp_h2o,
               const float* __restrict__ comp_h2o_sq,
               const float* __restrict__ comp_o3,
               const float* __restrict__ comp_co2,
               const float* __restrict__ comp_n2o,
               const float* __restrict__ comp_ch4,
               const float* __restrict__ comp_u,
               const float* __restrict__ lwp,
               const float* __restrict__ iwp,
               const float* __restrict__ mu,
               const float* __restrict__ mu_bar,
               const float* __restrict__ gas_W1,
               const float* __restrict__ gas_b1,
               const float* __restrict__ gas_W2,
               const float* __restrict__ gas_b2,
               const float* __restrict__ lw_w,
               const float* __restrict__ iw_w,
               const float* __restrict__ ext_W1,
               const float* __restrict__ ext_b1,
               const float* __restrict__ ext_W2,
               const float* __restrict__ ext_b2,
               float* __restrict__ out,
               int B)
{
    __shared__ SmemT sm;
    const int r = blockIdx.y;
    const int cnt = cCNT[r];
    #define ARGS &sm, r, temp, pressure, comp_h2o, comp_h2o_sq, comp_o3, comp_co2, \
                 comp_n2o, comp_ch4, comp_u, lwp, iwp, mu, mu_bar, gas_W1, gas_b1, \
                 gas_W2, gas_b2, lw_w, iw_w, ext_W1, ext_b1, ext_W2, ext_b2, out, B
    switch (cnt) {
        case 7: row_body<7>(ARGS); break;
        case 4: row_body<4>(ARGS); break;
        case 3: row_body<3>(ARGS); break;
        case 2: row_body<2>(ARGS); break;
        default: row_body<1>(ARGS); break;
    }
    #undef ARGS
}

extern "C" void kernel_launch(void* const* d_in, const int* in_sizes, int n_in,
                              void* d_out, int out_size)
{
    const int B = in_sizes[0];
    const int pairs = (B + 1) / 2;
    dim3 grid((pairs + TPB - 1) / TPB, 29);
    atm_row_kernel<<<grid, TPB>>>(
        (const float*)d_in[0],  (const float*)d_in[1],  (const float*)d_in[2],
        (const float*)d_in[3],  (const float*)d_in[4],  (const float*)d_in[5],
        (const float*)d_in[6],  (const float*)d_in[7],  (const float*)d_in[8],
        (const float*)d_in[9],  (const float*)d_in[10], (const float*)d_in[11],
        (const float*)d_in[12], (const float*)d_in[13], (const float*)d_in[14],
        (const float*)d_in[15], (const float*)d_in[16], (const float*)d_in[17],
        (const float*)d_in[18], (const float*)d_in[19], (const float*)d_in[20],
        (const float*)d_in[21], (const float*)d_in[22],
        (float*)d_out, B);
}

// round 11
// speedup vs baseline: 3.7471x; 1.2364x over previous
#include <cuda_runtime.h>

// AtmLayer v6: (row, column-pair) grid; f32x2-packed math across the (A,B)
// column pair with pre-duplicated weight pairs in smem; select-free gas elu
// via elu(z) = max(z,0) + exp(min(z,0)) - 1 with pre-scaled weights.

#define TPB 128

typedef unsigned long long u64;
union F2U { u64 u; float2 f; };

__device__ __forceinline__ float2 fma2(float2 a, float2 b, float2 c) {
    F2U A, B, C, D; A.f = a; B.f = b; C.f = c;
    asm("fma.rn.f32x2 %0,%1,%2,%3;" : "=l"(D.u) : "l"(A.u), "l"(B.u), "l"(C.u));
    return D.f;
}
__device__ __forceinline__ float2 mul2(float2 a, float2 b) {
    F2U A, B, D; A.f = a; B.f = b;
    asm("mul.rn.f32x2 %0,%1,%2;" : "=l"(D.u) : "l"(A.u), "l"(B.u));
    return D.f;
}
__device__ __forceinline__ float2 add2(float2 a, float2 b) {
    F2U A, B, D; A.f = a; B.f = b;
    asm("add.rn.f32x2 %0,%1,%2;" : "=l"(D.u) : "l"(A.u), "l"(B.u));
    return D.f;
}
__device__ __forceinline__ float ex2_(float x) {
    float r; asm("ex2.approx.ftz.f32 %0,%1;" : "=f"(r) : "f"(x)); return r;
}

#define L2E 1.4426950408889634f
#define LN2 0.6931471805599453f

// comp idx: 0=h2o 1=h2o_sq 2=o3 3=co2 4=n2o 5=ch4 6=u
__constant__ int cNETS[29][7] = {
    {23, 0,52,65,74,77,86},
    {24, 1,53,66,75,78,87},
    {25, 2,54,67,76,79,88},
    {26, 3,80,-1,-1,-1,-1},
    {27, 4,81,-1,-1,-1,-1},
    {28, 5,68,-1,-1,-1,-1},
    {29, 6,69,-1,-1,-1,-1},
    {30, 3,82,-1,-1,-1,-1},
    {31, 4,83,-1,-1,-1,-1},
    {32, 9,70,-1,-1,-1,-1},
    {33,10,71,-1,-1,-1,-1},
    {34,11,84,-1,-1,-1,-1},
    {35,12,85,-1,-1,-1,-1},
    {36,13,72,-1,-1,-1,-1},
    {37,14,73,-1,-1,-1,-1},
    {38,15,89,-1,-1,-1,-1},
    {39,16,90,-1,-1,-1,-1},
    {40,17,55,91,-1,-1,-1},
    {41,18,56,92,-1,-1,-1},
    {42,19,57,93,-1,-1,-1},
    {43,20,58,94,-1,-1,-1},
    {44,21,59,95,-1,-1,-1},
    {45,22,60,96,-1,-1,-1},
    {46,-1,-1,-1,-1,-1,-1},
    {47,-1,-1,-1,-1,-1,-1},
    {48,61,-1,-1,-1,-1,-1},
    {49,62,-1,-1,-1,-1,-1},
    {50,63,97,-1,-1,-1,-1},
    {51,64,98,-1,-1,-1,-1},
};
__constant__ int cCIDX[29][7] = {
    {1,0,2,3,4,5,6},
    {1,0,2,3,4,5,6},
    {1,0,2,3,4,5,6},
    {1,0,5,0,0,0,0},
    {1,0,5,0,0,0,0},
    {1,0,3,0,0,0,0},
    {1,0,3,0,0,0,0},
    {1,0,5,0,0,0,0},
    {1,0,5,0,0,0,0},
    {1,0,3,0,0,0,0},
    {1,0,3,0,0,0,0},
    {1,0,5,0,0,0,0},
    {1,0,5,0,0,0,0},
    {1,0,3,0,0,0,0},
    {1,0,3,0,0,0,0},
    {1,0,6,0,0,0,0},
    {1,0,6,0,0,0,0},
    {1,0,2,6,0,0,0},
    {1,0,2,6,0,0,0},
    {1,0,2,6,0,0,0},
    {1,0,2,6,0,0,0},
    {1,0,2,6,0,0,0},
    {1,0,2,6,0,0,0},
    {1,0,0,0,0,0,0},
    {1,0,0,0,0,0,0},
    {1,2,0,0,0,0,0},
    {1,2,0,0,0,0,0},
    {1,2,6,0,0,0,0},
    {1,2,6,0,0,0,0},
};
__constant__ int cCNT[29] = {7,7,7,3,3,3,3,3,3,3,3,3,3,3,3,3,3,4,4,4,4,4,4,1,1,2,2,3,3};

struct __align__(16) GasNet {
    float2 w1[16];   // W1 * log2e, duplicated pairs; index [i*8 + u]
    float2 b1[8];    // b1 * log2e, dup
    float2 vln[8];   // W2 * ln2, dup
    float2 v[8];     // W2, dup
    float  bias;     // b2 - sum(W2)
    float  pad;
};
struct __align__(16) SmemT {
    GasNet g[7];
    float2 ew1[16][4];   // ext W1 dup, [j][i]
    float2 ev[16][4];    // ext W2 dup, [j][k], k=3 zero
    float2 eb1[16];      // ext b1 dup
    float  misc[5];      // lw, iw, eb0..2
    const float* comp[7];
};

template<int CNT>
__device__ __forceinline__ void row_body(
    SmemT* sm, int r,
    const float* __restrict__ temp, const float* __restrict__ pressure,
    const float* __restrict__ comp_h2o, const float* __restrict__ comp_h2o_sq,
    const float* __restrict__ comp_o3, const float* __restrict__ comp_co2,
    const float* __restrict__ comp_n2o, const float* __restrict__ comp_ch4,
    const float* __restrict__ comp_u,
    const float* __restrict__ lwp, const float* __restrict__ iwp,
    const float* __restrict__ mu, const float* __restrict__ mu_bar,
    const float* __restrict__ gas_W1, const float* __restrict__ gas_b1,
    const float* __restrict__ gas_W2, const float* __restrict__ gas_b2,
    const float* __restrict__ lw_w, const float* __restrict__ iw_w,
    const float* __restrict__ ext_W1, const float* __restrict__ ext_b1,
    const float* __restrict__ ext_W2, const float* __restrict__ ext_b2,
    float* __restrict__ out, int B)
{
    const int tid = threadIdx.x;

    // ---- staging: transform + duplicate weights ----
    #pragma unroll 2
    for (int i = tid; i < CNT * 33; i += TPB) {
        const int t = i / 33;
        const int k = i - t * 33;
        const int g = cNETS[r][t];
        GasNet& G = sm->g[t];
        if (k < 16) {
            const float w = gas_W1[g * 16 + k] * L2E;
            G.w1[k] = make_float2(w, w);
        } else if (k < 24) {
            const float w = gas_b1[g * 8 + (k - 16)] * L2E;
            G.b1[k - 16] = make_float2(w, w);
        } else if (k < 32) {
            const float w = gas_W2[g * 8 + (k - 24)];
            G.vln[k - 24] = make_float2(w * LN2, w * LN2);
            G.v[k - 24]   = make_float2(w, w);
        } else {
            float s = 0.0f;
            #pragma unroll
            for (int u = 0; u < 8; ++u) s += gas_W2[g * 8 + u];
            G.bias = gas_b2[g] - s;
        }
    }
    for (int i = tid; i < 64; i += TPB) {
        const int ii = i >> 4, j = i & 15;
        const float w = ext_W1[r * 64 + i];
        sm->ew1[j][ii] = make_float2(w, w);
    }
    for (int i = tid; i < 48; i += TPB) {
        const int j = i / 3, k = i - j * 3;
        const float w = ext_W2[r * 48 + i];
        sm->ev[j][k] = make_float2(w, w);
    }
    for (int i = tid; i < 16; i += TPB) {
        sm->ev[i][3] = make_float2(0.0f, 0.0f);
        const float w = ext_b1[r * 16 + i];
        sm->eb1[i] = make_float2(w, w);
    }
    if (tid < 5) {
        float v;
        if      (tid == 0) v = lw_w[r];
        else if (tid == 1) v = iw_w[r];
        else               v = ext_b2[r * 3 + (tid - 2)];
        sm->misc[tid] = v;
    }
    if (tid >= 8 && tid < 8 + CNT) {
        const int t = tid - 8;
        const float* ptrs[7] = {comp_h2o, comp_h2o_sq, comp_o3, comp_co2,
                                comp_n2o, comp_ch4, comp_u};
        sm->comp[t] = ptrs[cCIDX[r][t]];
    }
    __syncthreads();

    const int p = blockIdx.x * TPB + tid;      // pair index
    const int b0 = 2 * p;
    if (b0 + 1 >= B) return;

    const float2 X0 = reinterpret_cast<const float2*>(temp)[p];      // (A,B)
    const float2 X1 = reinterpret_cast<const float2*>(pressure)[p];

    // ---- gas nets: packed (A,B), split-accumulator elu ----
    float2 tau = make_float2(0.0f, 0.0f);
    #pragma unroll
    for (int t = 0; t < CNT; ++t) {
        const GasNet& G = sm->g[t];
        float2 acc1 = make_float2(0.0f, 0.0f);
        float2 acc2 = make_float2(0.0f, 0.0f);
        #pragma unroll
        for (int u = 0; u < 8; ++u) {
            const float2 zs = fma2(X1, G.w1[8 + u], fma2(X0, G.w1[u], G.b1[u]));
            const float2 mx = make_float2(fmaxf(zs.x, 0.0f), fmaxf(zs.y, 0.0f));
            const float2 ee = make_float2(ex2_(fminf(zs.x, 0.0f)),
                                          ex2_(fminf(zs.y, 0.0f)));
            acc1 = fma2(mx, G.vln[u], acc1);
            acc2 = fma2(ee, G.v[u], acc2);
        }
        const float2 acc = add2(acc1, acc2);
        const float keA = fmaxf(acc.x + G.bias, 0.0f);
        const float keB = fmaxf(acc.y + G.bias, 0.0f);
        const float2 cc = reinterpret_cast<const float2*>(sm->comp[t])[p];
        tau = fma2(make_float2(keA, keB), cc, tau);
    }

    // ---- cloud terms + ext inputs ----
    const float2 LWP = reinterpret_cast<const float2*>(lwp)[p];
    const float2 IWP = reinterpret_cast<const float2*>(iwp)[p];
    const float2 MUv = reinterpret_cast<const float2*>(mu)[p];
    const float2 MUB = reinterpret_cast<const float2*>(mu_bar)[p];
    const float lwr = sm->misc[0], iwr = sm->misc[1];
    const float2 tlw = mul2(make_float2(lwr, lwr), LWP);
    const float2 tiw = mul2(make_float2(iwr, iwr), IWP);
    const float2 tt  = add2(tau, add2(tlw, tiw));
    const float rttA = __fdividef(1.0f, tt.x);
    const float rttB = __fdividef(1.0f, tt.y);
    const float2 rtt = make_float2(rttA, rttB);
    const float2 I1 = mul2(tlw, rtt);
    const float2 I2 = mul2(tiw, rtt);
    const float2 I3D = make_float2(tt.x * __fdividef(1.0f, MUv.x),
                                   tt.y * __fdividef(1.0f, MUv.y));
    const float2 I3F = make_float2(tt.x * __fdividef(1.0f, MUB.x),
                                   tt.y * __fdividef(1.0f, MUB.y));

    // ---- ext net: packed (A,B), direct+diffuse share weight loads ----
    const float eb0 = sm->misc[2], eb1v = sm->misc[3], eb2v = sm->misc[4];
    float2 ad0 = make_float2(eb0, eb0), ad1 = make_float2(eb1v, eb1v), ad2 = make_float2(eb2v, eb2v);
    float2 af0 = ad0, af1 = ad1, af2 = ad2;
    const float2 L2E2 = make_float2(L2E, L2E);
    #pragma unroll
    for (int j = 0; j < 16; ++j) {
        const float2 w0 = sm->ew1[j][0];
        const float2 w1v = sm->ew1[j][1];
        const float2 w2v = sm->ew1[j][2];
        const float2 w3v = sm->ew1[j][3];
        const float2 base = fma2(I2, w1v, fma2(I1, w0, sm->eb1[j]));
        const float2 zd = fma2(MUv, w3v, fma2(I3D, w2v, base));
        const float2 zf = fma2(MUB, w3v, fma2(I3F, w2v, base));
        const float2 td = mul2(zd, L2E2);
        const float2 tf = mul2(zf, L2E2);
        float2 hd, hf;
        hd.x = zd.x > 0.0f ? zd.x : ex2_(td.x) - 1.0f;
        hd.y = zd.y > 0.0f ? zd.y : ex2_(td.y) - 1.0f;
        hf.x = zf.x > 0.0f ? zf.x : ex2_(tf.x) - 1.0f;
        hf.y = zf.y > 0.0f ? zf.y : ex2_(tf.y) - 1.0f;
        const float2 v0 = sm->ev[j][0];
        const float2 v1 = sm->ev[j][1];
        const float2 v2 = sm->ev[j][2];
        ad0 = fma2(hd, v0, ad0); ad1 = fma2(hd, v1, ad1); ad2 = fma2(hd, v2, ad2);
        af0 = fma2(hf, v0, af0); af1 = fma2(hf, v1, af1); af2 = fma2(hf, v2, af2);
    }

    const unsigned NB = (unsigned)B * 29u;
    const unsigned rb = (unsigned)r * (unsigned)B + (unsigned)b0;
    const unsigned ebase = rb * 3u;

    // softmax (direct, cols A+B) -> 3 float2 stores
    {
        const float a0 = fmaxf(ad0.x, 0.0f), a1 = fmaxf(ad1.x, 0.0f), a2 = fmaxf(ad2.x, 0.0f);
        const float m = fmaxf(a0, fmaxf(a1, a2));
        const float e0 = ex2_((a0 - m) * L2E), e1 = ex2_((a1 - m) * L2E), e2 = ex2_((a2 - m) * L2E);
        const float inv = __fdividef(1.0f, e0 + e1 + e2);
        const float b0v = fmaxf(ad0.y, 0.0f), b1v = fmaxf(ad1.y, 0.0f), b2v = fmaxf(ad2.y, 0.0f);
        const float mB = fmaxf(b0v, fmaxf(b1v, b2v));
        const float f0 = ex2_((b0v - mB) * L2E), f1 = ex2_((b1v - mB) * L2E), f2 = ex2_((b2v - mB) * L2E);
        const float invB = __fdividef(1.0f, f0 + f1 + f2);
        float2* o = reinterpret_cast<float2*>(out + 2u * NB + ebase);
        o[0] = make_float2(e0 * inv, e1 * inv);
        o[1] = make_float2(e2 * inv, f0 * invB);
        o[2] = make_float2(f1 * invB, f2 * invB);
    }
    // softmax (diffuse)
    {
        const float a0 = fmaxf(af0.x, 0.0f), a1 = fmaxf(af1.x, 0.0f), a2 = fmaxf(af2.x, 0.0f);
        const float m = fmaxf(a0, fmaxf(a1, a2));
        const float e0 = ex2_((a0 - m) * L2E), e1 = ex2_((a1 - m) * L2E), e2 = ex2_((a2 - m) * L2E);
        const float inv = __fdividef(1.0f, e0 + e1 + e2);
        const float b0v = fmaxf(af0.y, 0.0f), b1v = fmaxf(af1.y, 0.0f), b2v = fmaxf(af2.y, 0.0f);
        const float mB = fmaxf(b0v, fmaxf(b1v, b2v));
        const float f0 = ex2_((b0v - mB) * L2E), f1 = ex2_((b1v - mB) * L2E), f2 = ex2_((b2v - mB) * L2E);
        const float invB = __fdividef(1.0f, f0 + f1 + f2);
        float2* o = reinterpret_cast<float2*>(out + 5u * NB + ebase);
        o[0] = make_float2(e0 * inv, e1 * inv);
        o[1] = make_float2(e2 * inv, f0 * invB);
        o[2] = make_float2(f1 * invB, f2 * invB);
    }
    {
        const float2 nd = mul2(I3D, make_float2(-L2E, -L2E));
        const float2 nf = mul2(I3F, make_float2(-L2E, -L2E));
        reinterpret_cast<float2*>(out + rb)[0]      = make_float2(ex2_(nd.x), ex2_(nd.y));
        reinterpret_cast<float2*>(out + NB + rb)[0] = make_float2(ex2_(nf.x), ex2_(nf.y));
    }
}

__global__ void __launch_bounds__(TPB)
atm_row_kernel(const float* __restrict__ temp,
               const float* __restrict__ pressure,
               const float* __restrict__ comp_h2o,
               const float* __restrict__ comp_h2o_sq,
               const float* __restrict__ comp_o3,
               const float* __restrict__ comp_co2,
               const float* __restrict__ comp_n2o,
               const float* __restrict__ comp_ch4,
               const float* __restrict__ comp_u,
               const float* __restrict__ lwp,
               const float* __restrict__ iwp,
               const float* __restrict__ mu,
               const float* __restrict__ mu_bar,
               const float* __restrict__ gas_W1,
               const float* __restrict__ gas_b1,
               const float* __restrict__ gas_W2,
               const float* __restrict__ gas_b2,
               const float* __restrict__ lw_w,
               const float* __restrict__ iw_w,
               const float* __restrict__ ext_W1,
               const float* __restrict__ ext_b1,
               const float* __restrict__ ext_W2,
               const float* __restrict__ ext_b2,
               float* __restrict__ out,
               int B)
{
    __shared__ SmemT sm;
    const int r = blockIdx.y;
    const int cnt = cCNT[r];
    #define ARGS &sm, r, temp, pressure, comp_h2o, comp_h2o_sq, comp_o3, comp_co2, \
                 comp_n2o, comp_ch4, comp_u, lwp, iwp, mu, mu_bar, gas_W1, gas_b1, \
                 gas_W2, gas_b2, lw_w, iw_w, ext_W1, ext_b1, ext_W2, ext_b2, out, B
    switch (cnt) {
        case 7: row_body<7>(ARGS); break;
        case 4: row_body<4>(ARGS); break;
        case 3: row_body<3>(ARGS); break;
        case 2: row_body<2>(ARGS); break;
        default: row_body<1>(ARGS); break;
    }
    #undef ARGS
}

extern "C" void kernel_launch(void* const* d_in, const int* in_sizes, int n_in,
                              void* d_out, int out_size)
{
    const int B = in_sizes[0];
    const int pairs = (B + 1) / 2;
    dim3 grid((pairs + TPB - 1) / TPB, 29);
    atm_row_kernel<<<grid, TPB>>>(
        (const float*)d_in[0],  (const float*)d_in[1],  (const float*)d_in[2],
        (const float*)d_in[3],  (const float*)d_in[4],  (const float*)d_in[5],
        (const float*)d_in[6],  (const float*)d_in[7],  (const float*)d_in[8],
        (const float*)d_in[9],  (const float*)d_in[10], (const float*)d_in[11],
        (const float*)d_in[12], (const float*)d_in[13], (const float*)d_in[14],
        (const float*)d_in[15], (const float*)d_in[16], (const float*)d_in[17],
        (const float*)d_in[18], (const float*)d_in[19], (const float*)d_in[20],
        (const float*)d_in[21], (const float*)d_in[22],
        (float*)d_out, B);
}